// round 15
// baseline (speedup 1.0000x reference)
#include <cuda_runtime.h>
#include <cuda_bf16.h>
#include <cstdint>

#define KEPS   0.001f
#define BH     64
#define SLEN   4096
#define DDIM   64
#define SPLITS 16
#define SCHUNK (SLEN / SPLITS)     // 256
#define NROWS  72                  // phase1 partial rows: 64 kv + ksum + 7 pad

// ---------------- scratch (__device__ globals; allocation-free rule) -------
__device__ float         g_pkv[SPLITS * BH * NROWS * DDIM];
__device__ __nv_bfloat16 g_bhi[BH * DDIM * DDIM];   // kv^T bf16 hi [64 n][64 k]
__device__ __nv_bfloat16 g_blo[BH * DDIM * DDIM];   // kv^T bf16 lo
__device__ float         g_ksum[BH * DDIM];         // fp32 ksum

// ---------------- helpers ---------------------------------------------------
__device__ __forceinline__ uint32_t s2u(const void* p) {
    uint32_t a;
    asm("{ .reg .u64 t; cvta.to.shared.u64 t, %1; cvt.u32.u64 %0, t; }"
        : "=r"(a) : "l"(p));
    return a;
}
__device__ __forceinline__ void mma16816(float* c, const uint32_t* a, const uint32_t* b) {
    asm volatile(
        "mma.sync.aligned.m16n8k16.row.col.f32.bf16.bf16.f32 "
        "{%0,%1,%2,%3}, {%4,%5,%6,%7}, {%8,%9}, {%0,%1,%2,%3};"
        : "+f"(c[0]), "+f"(c[1]), "+f"(c[2]), "+f"(c[3])
        : "r"(a[0]), "r"(a[1]), "r"(a[2]), "r"(a[3]), "r"(b[0]), "r"(b[1]));
}
__device__ __forceinline__ void ldsm_x4_t(uint32_t* r, uint32_t addr) {
    asm volatile("ldmatrix.sync.aligned.m8n8.x4.trans.shared.b16 {%0,%1,%2,%3}, [%4];"
        : "=r"(r[0]), "=r"(r[1]), "=r"(r[2]), "=r"(r[3]) : "r"(addr));
}
__device__ __forceinline__ void ldsm_x2(uint32_t* r, uint32_t addr) {
    asm volatile("ldmatrix.sync.aligned.m8n8.x2.shared.b16 {%0,%1}, [%2];"
        : "=r"(r[0]), "=r"(r[1]) : "r"(addr));
}
__device__ __forceinline__ void ldsm_x2_t(uint32_t* r, uint32_t addr) {
    asm volatile("ldmatrix.sync.aligned.m8n8.x2.trans.shared.b16 {%0,%1}, [%2];"
        : "=r"(r[0]), "=r"(r[1]) : "r"(addr));
}
// packed bf16x2 convert
__device__ __forceinline__ uint32_t cvt2(float hi, float lo) {
    uint32_t r;
    asm("cvt.rn.bf16x2.f32 %0, %1, %2;" : "=r"(r) : "f"(hi), "f"(lo));
    return r;
}
// split pair (x0,x1) into packed bf16x2 hi (H) and residual lo (L)
__device__ __forceinline__ void split2(float x0, float x1, uint32_t& H, uint32_t& L) {
    H = cvt2(x1, x0);
    float f0 = __uint_as_float(H << 16);
    float f1 = __uint_as_float(H & 0xFFFF0000u);
    L = cvt2(x1 - f1, x0 - f0);
}

// ---------------------------------------------------------------------------
// Phase 1 (HMMA): partial M[e,d] = sum_s v_ext[s,e] * k_eff[s,d] over S-chunk.
// (R8 verbatim + PDL trigger + trimmed mt=4 stores.)
// grid = (BH, SPLITS), block = 128 (4 warps; warp = 16-wide d-group).
// ---------------------------------------------------------------------------
__global__ __launch_bounds__(128, 3) void k_phase1(
    const float* __restrict__ key,
    const float* __restrict__ value,
    const float* __restrict__ mask)
{
    __shared__ __nv_bfloat16 skh[32][72], skl[32][72];   // k_eff hi/lo
    __shared__ __nv_bfloat16 svh[32][88], svl[32][88];   // v_ext hi/lo

    const int bh    = blockIdx.x;
    const int split = blockIdx.y;
    const int b     = bh >> 4;
    const int t     = threadIdx.x;
    const int warp  = t >> 5;            // d-group
    const int lane  = t & 31;

    // init v pad cols 64..87 (constant across windows)
    for (int i = t; i < 32 * 24; i += 128) {
        int row = i / 24, col = 64 + (i % 24);
        svh[row][col] = __float2bfloat16(col == 64 ? 1.0f : 0.0f);
        svl[row][col] = __float2bfloat16(0.0f);
    }

    float acc[5][2][4];
#pragma unroll
    for (int i = 0; i < 5; i++)
#pragma unroll
        for (int j = 0; j < 2; j++)
#pragma unroll
            for (int q = 0; q < 4; q++) acc[i][j][q] = 0.0f;

    const float* kp = key   + (size_t)bh * SLEN * DDIM;
    const float* vp = value + (size_t)bh * SLEN * DDIM;
    const float* mp = mask  + (size_t)b * SLEN;
    const int s0 = split * SCHUNK;

    const uint32_t a_kh = s2u(&skh[0][0]), a_kl = s2u(&skl[0][0]);
    const uint32_t a_vh = s2u(&svh[0][0]), a_vl = s2u(&svl[0][0]);

    const int grp = lane >> 3, jj = lane & 7, l15 = lane & 15;
    const int myrow = t >> 4;            // 0..7 (+8i -> 32 rows)
    const int myc4  = (t & 15) * 4;

    float4 kst[4], vst[4];
    float  mst[4];

    // stage window 0
#pragma unroll
    for (int i = 0; i < 4; i++) {
        int row = myrow + i * 8;
        kst[i] = __ldcs((const float4*)(kp + (size_t)(s0 + row) * DDIM + myc4));
        vst[i] = __ldcs((const float4*)(vp + (size_t)(s0 + row) * DDIM + myc4));
        mst[i] = mp[s0 + row];
    }

    const int nsteps = SCHUNK / 32;      // 8
    for (int step = 0; step < nsteps; step++) {
        __syncthreads();                 // previous MMA reads done
#pragma unroll
        for (int i = 0; i < 4; i++) {
            int row = myrow + i * 8;
            float m = mst[i];
            float em = KEPS * m;
            float x0 = fmaf(fmaxf(kst[i].x, 0.0f), m, em);
            float x1 = fmaf(fmaxf(kst[i].y, 0.0f), m, em);
            float x2 = fmaf(fmaxf(kst[i].z, 0.0f), m, em);
            float x3 = fmaf(fmaxf(kst[i].w, 0.0f), m, em);
            uint32_t H01, L01, H23, L23;
            split2(x0, x1, H01, L01);
            split2(x2, x3, H23, L23);
            *(uint2*)&skh[row][myc4] = make_uint2(H01, H23);
            *(uint2*)&skl[row][myc4] = make_uint2(L01, L23);

            split2(vst[i].x, vst[i].y, H01, L01);
            split2(vst[i].z, vst[i].w, H23, L23);
            *(uint2*)&svh[row][myc4] = make_uint2(H01, H23);
            *(uint2*)&svl[row][myc4] = make_uint2(L01, L23);
        }
        __syncthreads();

        // prefetch next window while MMAs run below
        if (step + 1 < nsteps) {
            const int sg = s0 + (step + 1) * 32;
#pragma unroll
            for (int i = 0; i < 4; i++) {
                int row = myrow + i * 8;
                kst[i] = __ldcs((const float4*)(kp + (size_t)(sg + row) * DDIM + myc4));
                vst[i] = __ldcs((const float4*)(vp + (size_t)(sg + row) * DDIM + myc4));
                mst[i] = mp[sg + row];
            }
        }

#pragma unroll
        for (int ks = 0; ks < 32; ks += 16) {
            uint32_t Bh[2][2], Bl[2][2];
#pragma unroll
            for (int nt = 0; nt < 2; nt++) {
                int d0 = warp * 16 + nt * 8;
                ldsm_x2_t(Bh[nt], a_kh + (uint32_t)(((ks + l15) * 72 + d0) * 2));
                ldsm_x2_t(Bl[nt], a_kl + (uint32_t)(((ks + l15) * 72 + d0) * 2));
            }
            const int vrow = ks + jj + ((grp >> 1) << 3);
#pragma unroll
            for (int mt = 0; mt < 5; mt++) {
                int e0 = mt * 16 + ((grp & 1) << 3);
                uint32_t Ah[4], Al[4];
                ldsm_x4_t(Ah, a_vh + (uint32_t)((vrow * 88 + e0) * 2));
                if (mt < 4)
                    ldsm_x4_t(Al, a_vl + (uint32_t)((vrow * 88 + e0) * 2));
#pragma unroll
                for (int nt = 0; nt < 2; nt++) {
                    mma16816(acc[mt][nt], Ah, Bh[nt]);
                    mma16816(acc[mt][nt], Ah, Bl[nt]);
                    if (mt < 4) mma16816(acc[mt][nt], Al, Bh[nt]);
                }
            }
        }
    }

    // allow dependent (reduce) grid to start launching while we store
    cudaTriggerProgrammaticLaunchCompletion();

    // store fp32 partials: e rows 0..64 only (rows 65-71 never read by reduce)
    float* pkv = g_pkv + ((size_t)(split * BH + bh)) * NROWS * DDIM;
    const int r = lane >> 2, c2 = (lane & 3) * 2;
#pragma unroll
    for (int mt = 0; mt < 5; mt++)
#pragma unroll
        for (int nt = 0; nt < 2; nt++) {
            int e = mt * 16 + r;
            int d = warp * 16 + nt * 8 + c2;
            if (mt < 4) {
                *(float2*)(pkv + e * DDIM + d) = make_float2(acc[mt][nt][0], acc[mt][nt][1]);
                *(float2*)(pkv + (e + 8) * DDIM + d) = make_float2(acc[mt][nt][2], acc[mt][nt][3]);
            } else if (r == 0) {        // only e == 64 (ksum row) is consumed
                *(float2*)(pkv + 64 * DDIM + d) = make_float2(acc[mt][nt][0], acc[mt][nt][1]);
            }
        }
}

// ---------------------------------------------------------------------------
// Reduce over splits -> kv^T bf16 hi/lo [64][64] + fp32 ksum[64].
// PDL: wait for phase1, trigger phase2 immediately.  grid = BH, block = 288.
// ---------------------------------------------------------------------------
__global__ __launch_bounds__(288) void k_reduce()
{
    cudaGridDependencySynchronize();     // phase1 writes visible after this
    cudaTriggerProgrammaticLaunchCompletion();

    const int bh = blockIdx.x;
    const int t  = threadIdx.x;
#pragma unroll
    for (int j = 0; j < 4; j++) {
        int lin = t + j * 288;               // float4 group index
        if (lin >= 1040) break;
        float4 s = make_float4(0.f, 0.f, 0.f, 0.f);
#pragma unroll
        for (int sp = 0; sp < SPLITS; sp++) {
            float4 v = *(const float4*)(g_pkv + ((size_t)(sp * BH + bh)) * NROWS * DDIM + lin * 4);
            s.x += v.x; s.y += v.y; s.z += v.z; s.w += v.w;
        }
        if (lin < 1024) {
            uint32_t H01, L01, H23, L23;
            split2(s.x, s.y, H01, L01);
            split2(s.z, s.w, H23, L23);
            *(uint2*)(g_bhi + (size_t)bh * DDIM * DDIM + lin * 4) = make_uint2(H01, H23);
            *(uint2*)(g_blo + (size_t)bh * DDIM * DDIM + lin * 4) = make_uint2(L01, L23);
        } else {
            *(float4*)(g_ksum + bh * DDIM + (lin - 1024) * 4) = s;
        }
    }
}

// ---------------------------------------------------------------------------
// Phase 2 (HMMA): num = Q_eff . B^T via bf16-split; denom = fp32 dot(q, ksum).
// 256-thread / 256-row CTAs: per-warp work IDENTICAL to R8 (32 rows/warp),
// but 16 warps/SM at (256,2) and half the B-tile fill traffic.
// Q prefetch before the PDL wait.  grid = (SLEN/256, BH), block = 256.
// ---------------------------------------------------------------------------
__global__ __launch_bounds__(256, 2) void k_phase2(
    const float* __restrict__ query,
    float* __restrict__ out)
{
    __shared__ __nv_bfloat16 sbh[DDIM * 72];   // B hi, [n][k] stride 72
    __shared__ __nv_bfloat16 sbl[DDIM * 72];   // B lo
    __shared__ float sks[DDIM];

    const uint32_t a_bh = s2u(sbh), a_bl = s2u(sbl);
    const int t    = threadIdx.x;
    const int warp = t >> 5;             // 0..7
    const int lane = t & 31;
    const int s0   = blockIdx.x * 256;
    const int bh   = blockIdx.y;

    const int l15 = lane & 15;
    const int fr  = lane >> 2;           // frag row 0..7
    const int fc  = (lane & 3) * 2;      // frag col pair

    const float* qp = query + (size_t)bh * SLEN * DDIM;

    // ---- Q prefetch (independent of reduce output) BEFORE the PDL wait ----
    float2 st[2][4];
#pragma unroll
    for (int pre = 0; pre < 2; pre++) {
        int r0 = s0 + warp * 32 + (pre & 1) * 16 + fr;
        int cc = (pre >> 1) * 16 + fc;
        st[pre][0] = __ldcs((const float2*)(qp + (size_t)r0 * DDIM + cc));
        st[pre][1] = __ldcs((const float2*)(qp + (size_t)(r0 + 8) * DDIM + cc));
        st[pre][2] = __ldcs((const float2*)(qp + (size_t)r0 * DDIM + cc + 8));
        st[pre][3] = __ldcs((const float2*)(qp + (size_t)(r0 + 8) * DDIM + cc + 8));
    }

    cudaGridDependencySynchronize();     // reduce's writes visible after this

    // ---- B tiles (512 uint4 per tile) + ksum ----
    {
        const uint4* gh = (const uint4*)(g_bhi + (size_t)bh * DDIM * DDIM);
        const uint4* gl = (const uint4*)(g_blo + (size_t)bh * DDIM * DDIM);
#pragma unroll
        for (int i = 0; i < 2; i++) {
            int lin = t + i * 256;           // 0..511
            int row = lin >> 3, col = (lin & 7) * 8;
            *(uint4*)((char*)sbh + (row * 72 + col) * 2) = gh[lin];
            *(uint4*)((char*)sbl + (row * 72 + col) * 2) = gl[lin];
        }
        if (t < DDIM) sks[t] = g_ksum[bh * DDIM + t];
    }
    __syncthreads();

    float acc[2][8][4];
#pragma unroll
    for (int i = 0; i < 2; i++)
#pragma unroll
        for (int j = 0; j < 8; j++)
#pragma unroll
            for (int q = 0; q < 4; q++) acc[i][j][q] = 0.0f;
    float den[2][2] = {{0.f, 0.f}, {0.f, 0.f}};

    uint32_t Bh[8][2], Bl[8][2];
    int cur_ks = -1;

#pragma unroll
    for (int it = 0; it < 8; it++) {
        const int ks = it >> 1;
        const int k0 = ks * 16;
        if (ks != cur_ks) {
            cur_ks = ks;
#pragma unroll
            for (int nt = 0; nt < 8; nt++) {
                uint32_t off = (uint32_t)(((nt * 8 + (l15 & 7)) * 72 + k0 + ((l15 >> 3) << 3)) * 2);
                ldsm_x2(Bh[nt], a_bh + off);
                ldsm_x2(Bl[nt], a_bl + off);
            }
        }

        float2 c0 = st[it & 1][0], c1 = st[it & 1][1];
        float2 c2 = st[it & 1][2], c3 = st[it & 1][3];
        if (it + 2 < 8) {
            int nit = it + 2;
            int r0 = s0 + warp * 32 + (nit & 1) * 16 + fr;
            int cc = (nit >> 1) * 16 + fc;
            st[it & 1][0] = __ldcs((const float2*)(qp + (size_t)r0 * DDIM + cc));
            st[it & 1][1] = __ldcs((const float2*)(qp + (size_t)(r0 + 8) * DDIM + cc));
            st[it & 1][2] = __ldcs((const float2*)(qp + (size_t)r0 * DDIM + cc + 8));
            st[it & 1][3] = __ldcs((const float2*)(qp + (size_t)(r0 + 8) * DDIM + cc + 8));
        }

        // convert: relu+eps, packed bf16 split
        const int mt = it & 1;
        uint32_t Ah[4], Al[4];
        {
            float x0 = fmaxf(c0.x, 0.0f) + KEPS, x1 = fmaxf(c0.y, 0.0f) + KEPS;
            float y0 = fmaxf(c1.x, 0.0f) + KEPS, y1 = fmaxf(c1.y, 0.0f) + KEPS;
            float z0 = fmaxf(c2.x, 0.0f) + KEPS, z1 = fmaxf(c2.y, 0.0f) + KEPS;
            float w0 = fmaxf(c3.x, 0.0f) + KEPS, w1 = fmaxf(c3.y, 0.0f) + KEPS;
            split2(x0, x1, Ah[0], Al[0]);
            split2(y0, y1, Ah[1], Al[1]);
            split2(z0, z1, Ah[2], Al[2]);
            split2(w0, w1, Ah[3], Al[3]);

            // fp32 denominator partial dot with ksum
            float k0s = sks[k0 + fc],     k1s = sks[k0 + fc + 1];
            float k8s = sks[k0 + fc + 8], k9s = sks[k0 + fc + 9];
            den[mt][0] += x0 * k0s + x1 * k1s + z0 * k8s + z1 * k9s;
            den[mt][1] += y0 * k0s + y1 * k1s + w0 * k8s + w1 * k9s;
        }

#pragma unroll
        for (int nt = 0; nt < 8; nt++) {
            mma16816(acc[mt][nt], Ah, Bh[nt]);
            mma16816(acc[mt][nt], Ah, Bl[nt]);
            mma16816(acc[mt][nt], Al, Bh[nt]);
        }
    }

    // ---- epilogue: quad-reduce denominators, divide, direct STG ----
#pragma unroll
    for (int mt = 0; mt < 2; mt++) {
#pragma unroll
        for (int h = 0; h < 2; h++) {
            den[mt][h] += __shfl_xor_sync(0xffffffffu, den[mt][h], 1);
            den[mt][h] += __shfl_xor_sync(0xffffffffu, den[mt][h], 2);
        }
        float ilo = 1.0f / den[mt][0];
        float ihi = 1.0f / den[mt][1];
        int r0 = s0 + warp * 32 + mt * 16 + fr;
        float* ob0 = out + ((size_t)bh * SLEN + r0) * DDIM;
        float* ob1 = out + ((size_t)bh * SLEN + r0 + 8) * DDIM;
#pragma unroll
        for (int nt = 0; nt < 8; nt++) {
            int c = nt * 8 + fc;
            __stcs((float2*)(ob0 + c), make_float2(acc[mt][nt][0] * ilo, acc[mt][nt][1] * ilo));
            __stcs((float2*)(ob1 + c), make_float2(acc[mt][nt][2] * ihi, acc[mt][nt][3] * ihi));
        }
    }
}

// ---------------------------------------------------------------------------
extern "C" void kernel_launch(void* const* d_in, const int* in_sizes, int n_in,
                              void* d_out, int out_size)
{
    const float* query = (const float*)d_in[0];
    const float* key   = (const float*)d_in[1];
    const float* value = (const float*)d_in[2];
    const float* mask  = (const float*)d_in[3];
    float* out = (float*)d_out;

    // phase1: plain launch
    k_phase1<<<dim3(BH, SPLITS), 128>>>(key, value, mask);

    // reduce + phase2: programmatic dependent launches (overlap boundaries)
    cudaLaunchAttribute attr[1];
    attr[0].id = cudaLaunchAttributeProgrammaticStreamSerialization;
    attr[0].val.programmaticStreamSerializationAllowed = 1;

    {
        cudaLaunchConfig_t cfg = {};
        cfg.gridDim  = dim3(BH);
        cfg.blockDim = dim3(288);
        cfg.attrs    = attr;
        cfg.numAttrs = 1;
        cudaLaunchKernelEx(&cfg, k_reduce);
    }
    {
        cudaLaunchConfig_t cfg = {};
        cfg.gridDim  = dim3(SLEN / 256, BH);
        cfg.blockDim = dim3(256);
        cfg.attrs    = attr;
        cfg.numAttrs = 1;
        cudaLaunchKernelEx(&cfg, k_phase2, query, out);
    }
}

// round 16
// speedup vs baseline: 1.0127x; 1.0127x over previous
#include <cuda_runtime.h>
#include <cuda_bf16.h>
#include <cstdint>

#define KEPS   0.001f
#define BH     64
#define SLEN   4096
#define DDIM   64
#define SPLITS 16
#define SCHUNK (SLEN / SPLITS)     // 256
#define NROWS  72                  // phase1 partial rows: 64 kv + ksum (+pad)

// ---------------- scratch (__device__ globals; allocation-free rule) -------
__device__ float         g_pkv[SPLITS * BH * NROWS * DDIM];
__device__ __nv_bfloat16 g_bhi[BH * DDIM * DDIM];   // kv^T bf16 hi [64 n][64 k]
__device__ __nv_bfloat16 g_blo[BH * DDIM * DDIM];   // kv^T bf16 lo
__device__ float         g_ksum[BH * DDIM];         // fp32 ksum

// ---------------- helpers ---------------------------------------------------
__device__ __forceinline__ uint32_t s2u(const void* p) {
    uint32_t a;
    asm("{ .reg .u64 t; cvta.to.shared.u64 t, %1; cvt.u32.u64 %0, t; }"
        : "=r"(a) : "l"(p));
    return a;
}
__device__ __forceinline__ void mma16816(float* c, const uint32_t* a, const uint32_t* b) {
    asm volatile(
        "mma.sync.aligned.m16n8k16.row.col.f32.bf16.bf16.f32 "
        "{%0,%1,%2,%3}, {%4,%5,%6,%7}, {%8,%9}, {%0,%1,%2,%3};"
        : "+f"(c[0]), "+f"(c[1]), "+f"(c[2]), "+f"(c[3])
        : "r"(a[0]), "r"(a[1]), "r"(a[2]), "r"(a[3]), "r"(b[0]), "r"(b[1]));
}
__device__ __forceinline__ void ldsm_x4_t(uint32_t* r, uint32_t addr) {
    asm volatile("ldmatrix.sync.aligned.m8n8.x4.trans.shared.b16 {%0,%1,%2,%3}, [%4];"
        : "=r"(r[0]), "=r"(r[1]), "=r"(r[2]), "=r"(r[3]) : "r"(addr));
}
__device__ __forceinline__ void ldsm_x2(uint32_t* r, uint32_t addr) {
    asm volatile("ldmatrix.sync.aligned.m8n8.x2.shared.b16 {%0,%1}, [%2];"
        : "=r"(r[0]), "=r"(r[1]) : "r"(addr));
}
__device__ __forceinline__ void ldsm_x2_t(uint32_t* r, uint32_t addr) {
    asm volatile("ldmatrix.sync.aligned.m8n8.x2.trans.shared.b16 {%0,%1}, [%2];"
        : "=r"(r[0]), "=r"(r[1]) : "r"(addr));
}
// packed bf16x2 convert
__device__ __forceinline__ uint32_t cvt2(float hi, float lo) {
    uint32_t r;
    asm("cvt.rn.bf16x2.f32 %0, %1, %2;" : "=r"(r) : "f"(hi), "f"(lo));
    return r;
}
// split pair (x0,x1) into packed bf16x2 hi (H) and residual lo (L)
__device__ __forceinline__ void split2(float x0, float x1, uint32_t& H, uint32_t& L) {
    H = cvt2(x1, x0);
    float f0 = __uint_as_float(H << 16);
    float f1 = __uint_as_float(H & 0xFFFF0000u);
    L = cvt2(x1 - f1, x0 - f0);
}

// ---------------------------------------------------------------------------
// Phase 1 (HMMA): partial M[e,d] = sum_s v[s,e] * k_eff[s,d] over S-chunk
// (e tiles 0..3 only); ksum[d] accumulated in SCALAR fp32 during conversion
// (replaces the old ones-column MMA tile: -4 MMAs, -1 ldsm per ks-step).
// grid = (BH, SPLITS), block = 128 (4 warps; warp = 16-wide d-group).
// ---------------------------------------------------------------------------
__global__ __launch_bounds__(128, 3) void k_phase1(
    const float* __restrict__ key,
    const float* __restrict__ value,
    const float* __restrict__ mask)
{
    __shared__ __nv_bfloat16 skh[32][72], skl[32][72];   // k_eff hi/lo
    __shared__ __nv_bfloat16 svh[32][72], svl[32][72];   // v hi/lo

    const int bh    = blockIdx.x;
    const int split = blockIdx.y;
    const int b     = bh >> 4;
    const int t     = threadIdx.x;
    const int warp  = t >> 5;            // d-group
    const int lane  = t & 31;

    float acc[4][2][4];
#pragma unroll
    for (int i = 0; i < 4; i++)
#pragma unroll
        for (int j = 0; j < 2; j++)
#pragma unroll
            for (int q = 0; q < 4; q++) acc[i][j][q] = 0.0f;
    float ks[4] = {0.f, 0.f, 0.f, 0.f};  // scalar ksum partials (cols myc4..+3)

    const float* kp = key   + (size_t)bh * SLEN * DDIM;
    const float* vp = value + (size_t)bh * SLEN * DDIM;
    const float* mp = mask  + (size_t)b * SLEN;
    const int s0 = split * SCHUNK;

    const uint32_t a_kh = s2u(&skh[0][0]), a_kl = s2u(&skl[0][0]);
    const uint32_t a_vh = s2u(&svh[0][0]), a_vl = s2u(&svl[0][0]);

    const int grp = lane >> 3, jj = lane & 7, l15 = lane & 15;
    const int myrow = t >> 4;            // 0..7 (+8i -> 32 rows)
    const int myc4  = (t & 15) * 4;

    float4 kst[4], vst[4];
    float  mst[4];

    // stage window 0
#pragma unroll
    for (int i = 0; i < 4; i++) {
        int row = myrow + i * 8;
        kst[i] = __ldcs((const float4*)(kp + (size_t)(s0 + row) * DDIM + myc4));
        vst[i] = __ldcs((const float4*)(vp + (size_t)(s0 + row) * DDIM + myc4));
        mst[i] = mp[s0 + row];
    }

    const int nsteps = SCHUNK / 32;      // 8
    for (int step = 0; step < nsteps; step++) {
        __syncthreads();                 // previous MMA reads done
#pragma unroll
        for (int i = 0; i < 4; i++) {
            int row = myrow + i * 8;
            float m = mst[i];
            float em = KEPS * m;
            float x0 = fmaf(fmaxf(kst[i].x, 0.0f), m, em);
            float x1 = fmaf(fmaxf(kst[i].y, 0.0f), m, em);
            float x2 = fmaf(fmaxf(kst[i].z, 0.0f), m, em);
            float x3 = fmaf(fmaxf(kst[i].w, 0.0f), m, em);
            ks[0] += x0; ks[1] += x1; ks[2] += x2; ks[3] += x3;
            uint32_t H01, L01, H23, L23;
            split2(x0, x1, H01, L01);
            split2(x2, x3, H23, L23);
            *(uint2*)&skh[row][myc4] = make_uint2(H01, H23);
            *(uint2*)&skl[row][myc4] = make_uint2(L01, L23);

            split2(vst[i].x, vst[i].y, H01, L01);
            split2(vst[i].z, vst[i].w, H23, L23);
            *(uint2*)&svh[row][myc4] = make_uint2(H01, H23);
            *(uint2*)&svl[row][myc4] = make_uint2(L01, L23);
        }
        __syncthreads();

        // prefetch next window while MMAs run below
        if (step + 1 < nsteps) {
            const int sg = s0 + (step + 1) * 32;
#pragma unroll
            for (int i = 0; i < 4; i++) {
                int row = myrow + i * 8;
                kst[i] = __ldcs((const float4*)(kp + (size_t)(sg + row) * DDIM + myc4));
                vst[i] = __ldcs((const float4*)(vp + (size_t)(sg + row) * DDIM + myc4));
                mst[i] = mp[sg + row];
            }
        }

#pragma unroll
        for (int ks_ = 0; ks_ < 32; ks_ += 16) {
            uint32_t Bh[2][2], Bl[2][2];
#pragma unroll
            for (int nt = 0; nt < 2; nt++) {
                int d0 = warp * 16 + nt * 8;
                ldsm_x2_t(Bh[nt], a_kh + (uint32_t)(((ks_ + l15) * 72 + d0) * 2));
                ldsm_x2_t(Bl[nt], a_kl + (uint32_t)(((ks_ + l15) * 72 + d0) * 2));
            }
            const int vrow = ks_ + jj + ((grp >> 1) << 3);
#pragma unroll
            for (int mt = 0; mt < 4; mt++) {
                int e0 = mt * 16 + ((grp & 1) << 3);
                uint32_t Ah[4], Al[4];
                ldsm_x4_t(Ah, a_vh + (uint32_t)((vrow * 72 + e0) * 2));
                ldsm_x4_t(Al, a_vl + (uint32_t)((vrow * 72 + e0) * 2));
#pragma unroll
                for (int nt = 0; nt < 2; nt++) {
                    mma16816(acc[mt][nt], Ah, Bh[nt]);
                    mma16816(acc[mt][nt], Ah, Bl[nt]);
                    mma16816(acc[mt][nt], Al, Bh[nt]);
                }
            }
        }
    }

    // allow dependent (reduce) grid to start launching while we store
    cudaTriggerProgrammaticLaunchCompletion();

    float* pkv = g_pkv + ((size_t)(split * BH + bh)) * NROWS * DDIM;

    // ---- ksum: deterministic 8-way smem reduction over row-groups ----
    __syncthreads();                     // smem free for reuse
    float* sred = (float*)&skh[0][0];    // 8 x 64 floats
    sred[myrow * 64 + myc4 + 0] = ks[0];
    sred[myrow * 64 + myc4 + 1] = ks[1];
    sred[myrow * 64 + myc4 + 2] = ks[2];
    sred[myrow * 64 + myc4 + 3] = ks[3];
    __syncthreads();
    if (t < 64) {
        float s = 0.0f;
#pragma unroll
        for (int i = 0; i < 8; i++) s += sred[i * 64 + t];
        pkv[64 * DDIM + t] = s;
    }

    // store fp32 partials [e 0..63][d 64]
    const int r = lane >> 2, c2 = (lane & 3) * 2;
#pragma unroll
    for (int mt = 0; mt < 4; mt++)
#pragma unroll
        for (int nt = 0; nt < 2; nt++) {
            int e = mt * 16 + r;
            int d = warp * 16 + nt * 8 + c2;
            *(float2*)(pkv + e * DDIM + d) = make_float2(acc[mt][nt][0], acc[mt][nt][1]);
            *(float2*)(pkv + (e + 8) * DDIM + d) = make_float2(acc[mt][nt][2], acc[mt][nt][3]);
        }
}

// ---------------------------------------------------------------------------
// Reduce over splits -> kv^T bf16 hi/lo [64][64] + fp32 ksum[64].
// PDL: wait for phase1, trigger phase2 immediately.  grid = BH, block = 288.
// ---------------------------------------------------------------------------
__global__ __launch_bounds__(288) void k_reduce()
{
    cudaGridDependencySynchronize();     // phase1 writes visible after this
    cudaTriggerProgrammaticLaunchCompletion();

    const int bh = blockIdx.x;
    const int t  = threadIdx.x;
#pragma unroll
    for (int j = 0; j < 4; j++) {
        int lin = t + j * 288;               // float4 group index
        if (lin >= 1040) break;
        float4 s = make_float4(0.f, 0.f, 0.f, 0.f);
#pragma unroll
        for (int sp = 0; sp < SPLITS; sp++) {
            float4 v = *(const float4*)(g_pkv + ((size_t)(sp * BH + bh)) * NROWS * DDIM + lin * 4);
            s.x += v.x; s.y += v.y; s.z += v.z; s.w += v.w;
        }
        if (lin < 1024) {
            uint32_t H01, L01, H23, L23;
            split2(s.x, s.y, H01, L01);
            split2(s.z, s.w, H23, L23);
            *(uint2*)(g_bhi + (size_t)bh * DDIM * DDIM + lin * 4) = make_uint2(H01, H23);
            *(uint2*)(g_blo + (size_t)bh * DDIM * DDIM + lin * 4) = make_uint2(L01, L23);
        } else {
            *(float4*)(g_ksum + bh * DDIM + (lin - 1024) * 4) = s;
        }
    }
}

// ---------------------------------------------------------------------------
// Phase 2 (HMMA): num = Q_eff . B^T via bf16-split; denom = fp32 dot(q, ksum).
// 256-thread / 256-row CTAs (R15 verbatim).  grid = (SLEN/256, BH).
// ---------------------------------------------------------------------------
__global__ __launch_bounds__(256, 2) void k_phase2(
    const float* __restrict__ query,
    float* __restrict__ out)
{
    __shared__ __nv_bfloat16 sbh[DDIM * 72];   // B hi, [n][k] stride 72
    __shared__ __nv_bfloat16 sbl[DDIM * 72];   // B lo
    __shared__ float sks[DDIM];

    const uint32_t a_bh = s2u(sbh), a_bl = s2u(sbl);
    const int t    = threadIdx.x;
    const int warp = t >> 5;             // 0..7
    const int lane = t & 31;
    const int s0   = blockIdx.x * 256;
    const int bh   = blockIdx.y;

    const int l15 = lane & 15;
    const int fr  = lane >> 2;           // frag row 0..7
    const int fc  = (lane & 3) * 2;      // frag col pair

    const float* qp = query + (size_t)bh * SLEN * DDIM;

    // ---- Q prefetch (independent of reduce output) BEFORE the PDL wait ----
    float2 st[2][4];
#pragma unroll
    for (int pre = 0; pre < 2; pre++) {
        int r0 = s0 + warp * 32 + (pre & 1) * 16 + fr;
        int cc = (pre >> 1) * 16 + fc;
        st[pre][0] = __ldcs((const float2*)(qp + (size_t)r0 * DDIM + cc));
        st[pre][1] = __ldcs((const float2*)(qp + (size_t)(r0 + 8) * DDIM + cc));
        st[pre][2] = __ldcs((const float2*)(qp + (size_t)r0 * DDIM + cc + 8));
        st[pre][3] = __ldcs((const float2*)(qp + (size_t)(r0 + 8) * DDIM + cc + 8));
    }

    cudaGridDependencySynchronize();     // reduce's writes visible after this

    // ---- B tiles (512 uint4 per tile) + ksum ----
    {
        const uint4* gh = (const uint4*)(g_bhi + (size_t)bh * DDIM * DDIM);
        const uint4* gl = (const uint4*)(g_blo + (size_t)bh * DDIM * DDIM);
#pragma unroll
        for (int i = 0; i < 2; i++) {
            int lin = t + i * 256;           // 0..511
            int row = lin >> 3, col = (lin & 7) * 8;
            *(uint4*)((char*)sbh + (row * 72 + col) * 2) = gh[lin];
            *(uint4*)((char*)sbl + (row * 72 + col) * 2) = gl[lin];
        }
        if (t < DDIM) sks[t] = g_ksum[bh * DDIM + t];
    }
    __syncthreads();

    float acc[2][8][4];
#pragma unroll
    for (int i = 0; i < 2; i++)
#pragma unroll
        for (int j = 0; j < 8; j++)
#pragma unroll
            for (int q = 0; q < 4; q++) acc[i][j][q] = 0.0f;
    float den[2][2] = {{0.f, 0.f}, {0.f, 0.f}};

    uint32_t Bh[8][2], Bl[8][2];
    int cur_ks = -1;

#pragma unroll
    for (int it = 0; it < 8; it++) {
        const int ks = it >> 1;
        const int k0 = ks * 16;
        if (ks != cur_ks) {
            cur_ks = ks;
#pragma unroll
            for (int nt = 0; nt < 8; nt++) {
                uint32_t off = (uint32_t)(((nt * 8 + (l15 & 7)) * 72 + k0 + ((l15 >> 3) << 3)) * 2);
                ldsm_x2(Bh[nt], a_bh + off);
                ldsm_x2(Bl[nt], a_bl + off);
            }
        }

        float2 c0 = st[it & 1][0], c1 = st[it & 1][1];
        float2 c2 = st[it & 1][2], c3 = st[it & 1][3];
        if (it + 2 < 8) {
            int nit = it + 2;
            int r0 = s0 + warp * 32 + (nit & 1) * 16 + fr;
            int cc = (nit >> 1) * 16 + fc;
            st[it & 1][0] = __ldcs((const float2*)(qp + (size_t)r0 * DDIM + cc));
            st[it & 1][1] = __ldcs((const float2*)(qp + (size_t)(r0 + 8) * DDIM + cc));
            st[it & 1][2] = __ldcs((const float2*)(qp + (size_t)r0 * DDIM + cc + 8));
            st[it & 1][3] = __ldcs((const float2*)(qp + (size_t)(r0 + 8) * DDIM + cc + 8));
        }

        // convert: relu+eps, packed bf16 split
        const int mt = it & 1;
        uint32_t Ah[4], Al[4];
        {
            float x0 = fmaxf(c0.x, 0.0f) + KEPS, x1 = fmaxf(c0.y, 0.0f) + KEPS;
            float y0 = fmaxf(c1.x, 0.0f) + KEPS, y1 = fmaxf(c1.y, 0.0f) + KEPS;
            float z0 = fmaxf(c2.x, 0.0f) + KEPS, z1 = fmaxf(c2.y, 0.0f) + KEPS;
            float w0 = fmaxf(c3.x, 0.0f) + KEPS, w1 = fmaxf(c3.y, 0.0f) + KEPS;
            split2(x0, x1, Ah[0], Al[0]);
            split2(y0, y1, Ah[1], Al[1]);
            split2(z0, z1, Ah[2], Al[2]);
            split2(w0, w1, Ah[3], Al[3]);

            // fp32 denominator partial dot with ksum
            float k0s = sks[k0 + fc],     k1s = sks[k0 + fc + 1];
            float k8s = sks[k0 + fc + 8], k9s = sks[k0 + fc + 9];
            den[mt][0] += x0 * k0s + x1 * k1s + z0 * k8s + z1 * k9s;
            den[mt][1] += y0 * k0s + y1 * k1s + w0 * k8s + w1 * k9s;
        }

#pragma unroll
        for (int nt = 0; nt < 8; nt++) {
            mma16816(acc[mt][nt], Ah, Bh[nt]);
            mma16816(acc[mt][nt], Ah, Bl[nt]);
            mma16816(acc[mt][nt], Al, Bh[nt]);
        }
    }

    // ---- epilogue: quad-reduce denominators, divide, direct STG ----
#pragma unroll
    for (int mt = 0; mt < 2; mt++) {
#pragma unroll
        for (int h = 0; h < 2; h++) {
            den[mt][h] += __shfl_xor_sync(0xffffffffu, den[mt][h], 1);
            den[mt][h] += __shfl_xor_sync(0xffffffffu, den[mt][h], 2);
        }
        float ilo = 1.0f / den[mt][0];
        float ihi = 1.0f / den[mt][1];
        int r0 = s0 + warp * 32 + mt * 16 + fr;
        float* ob0 = out + ((size_t)bh * SLEN + r0) * DDIM;
        float* ob1 = out + ((size_t)bh * SLEN + r0 + 8) * DDIM;
#pragma unroll
        for (int nt = 0; nt < 8; nt++) {
            int c = nt * 8 + fc;
            __stcs((float2*)(ob0 + c), make_float2(acc[mt][nt][0] * ilo, acc[mt][nt][1] * ilo));
            __stcs((float2*)(ob1 + c), make_float2(acc[mt][nt][2] * ihi, acc[mt][nt][3] * ihi));
        }
    }
}

// ---------------------------------------------------------------------------
extern "C" void kernel_launch(void* const* d_in, const int* in_sizes, int n_in,
                              void* d_out, int out_size)
{
    const float* query = (const float*)d_in[0];
    const float* key   = (const float*)d_in[1];
    const float* value = (const float*)d_in[2];
    const float* mask  = (const float*)d_in[3];
    float* out = (float*)d_out;

    // phase1: plain launch
    k_phase1<<<dim3(BH, SPLITS), 128>>>(key, value, mask);

    // reduce + phase2: programmatic dependent launches (overlap boundaries)
    cudaLaunchAttribute attr[1];
    attr[0].id = cudaLaunchAttributeProgrammaticStreamSerialization;
    attr[0].val.programmaticStreamSerializationAllowed = 1;

    {
        cudaLaunchConfig_t cfg = {};
        cfg.gridDim  = dim3(BH);
        cfg.blockDim = dim3(288);
        cfg.attrs    = attr;
        cfg.numAttrs = 1;
        cudaLaunchKernelEx(&cfg, k_reduce);
    }
    {
        cudaLaunchConfig_t cfg = {};
        cfg.gridDim  = dim3(SLEN / 256, BH);
        cfg.blockDim = dim3(256);
        cfg.attrs    = attr;
        cfg.numAttrs = 1;
        cudaLaunchKernelEx(&cfg, k_phase2, query, out);
    }
}